// round 5
// baseline (speedup 1.0000x reference)
#include <cuda_runtime.h>
#include <cuda_fp16.h>
#include <cuda_bf16.h>

#define Bz 256
#define Sz 512
#define Ez 100
#define Hz 64
#define Gz 256      // 4*H
#define Vz 50000
#define VP 50048    // padded vocab rows
#define NC 512      // 2 dirs * 256 gates

// Precomputed per-vocab input projections (+bias), fp16, layout [VP][NC]
__device__ __half g_tableh[(size_t)VP * NC];   // 51.2 MB -> L2-resident
__device__ float  g_hfin[2 * Bz * Hz];

// ---- f32x2 packed-math helpers ----
#define FMA2(acc, a, b) \
    asm("fma.rn.f32x2 %0, %1, %2, %0;" : "+l"(acc) : "l"(a), "l"(b))
#define ADD2(d, a, b) \
    asm("add.rn.f32x2 %0, %1, %2;" : "=l"(d) : "l"(a), "l"(b))
#define DUP2(d, a) \
    asm("mov.b64 %0, {%1, %1};" : "=l"(d) : "f"(a))
#define PACK2(d, a, b) \
    asm("mov.b64 %0, {%1, %2};" : "=l"(d) : "f"(a), "f"(b))
#define UNPACK2(a, b, d) \
    asm("mov.b64 {%0, %1}, %2;" : "=f"(a), "=f"(b) : "l"(d))

__device__ __forceinline__ float tanh_ap(float x) {
    float y;
    asm("tanh.approx.f32 %0, %1;" : "=f"(y) : "f"(x));
    return y;
}
__device__ __forceinline__ float sigm_t(float x) {
    return fmaf(0.5f, tanh_ap(0.5f * x), 0.5f);
}

// ---------------------------------------------------------------------------
// Kernel 1: vocab-table GEMM (fp32 math, fp16 store).
//   table[v, dir*256+g] = sum_k emb[v,k]*W_ih[g,k] + (b_ih[g]+b_hh[g])
//   Tile 128x64, 256 thr, 8x4 microtile, f32x2 packed on N.
// ---------------------------------------------------------------------------
#define TKc 50
#define LDAa 132   // A smem row stride (floats)
#define LDBb 68    // B smem row stride

__global__ __launch_bounds__(256)
void vocab_gemm(const float* __restrict__ emb,
                const float* __restrict__ Wih_f,
                const float* __restrict__ bih_f,
                const float* __restrict__ bhh_f,
                const float* __restrict__ Wih_b,
                const float* __restrict__ bih_b,
                const float* __restrict__ bhh_b)
{
    const int tid = threadIdx.x;
    const int tx = tid & 15;           // N microtile (4 cols)
    const int ty = tid >> 4;           // M microtile (8 rows)
    const int rb = blockIdx.x * 128;
    const int cb = blockIdx.y * 64;
    const int dir = cb >> 8;
    const int gb  = cb & 255;

    const float* __restrict__ W  = dir ? Wih_b : Wih_f;
    const float* __restrict__ bi = dir ? bih_b : bih_f;
    const float* __restrict__ bh = dir ? bhh_b : bhh_f;

    __shared__ __align__(16) float As[TKc * LDAa];
    __shared__ __align__(16) float Bs[TKc * LDBb];
    __shared__ float bias_s[64];

    if (tid < 64) bias_s[tid] = bi[gb + tid] + bh[gb + tid];

    unsigned long long acc[8][2];
#pragma unroll
    for (int i = 0; i < 8; i++) { acc[i][0] = 0ull; acc[i][1] = 0ull; }

    const float2* __restrict__ emb2 = (const float2*)emb;
    const float2* __restrict__ W2   = (const float2*)W;

    for (int kc = 0; kc < Ez; kc += TKc) {
        if (kc) __syncthreads();
        for (int p = tid; p < 128 * 25; p += 256) {
            int q = p % 25;
            int m = p / 25;
            int row = rb + m; if (row >= Vz) row = Vz - 1;
            float2 va = emb2[(size_t)row * 50 + (kc >> 1) + q];
            As[(2 * q)     * LDAa + m] = va.x;
            As[(2 * q + 1) * LDAa + m] = va.y;
        }
        for (int p = tid; p < 64 * 25; p += 256) {
            int q = p % 25;
            int m = p / 25;
            float2 vb = W2[(size_t)(gb + m) * 50 + (kc >> 1) + q];
            Bs[(2 * q)     * LDBb + m] = vb.x;
            Bs[(2 * q + 1) * LDBb + m] = vb.y;
        }
        __syncthreads();

#pragma unroll 5
        for (int k = 0; k < TKc; k++) {
            float4 aA = *(const float4*)(As + k * LDAa + ty * 8);
            float4 aB = *(const float4*)(As + k * LDAa + ty * 8 + 4);
            ulonglong2 b2 = *(const ulonglong2*)(Bs + k * LDBb + tx * 4);
            unsigned long long ad[8];
            DUP2(ad[0], aA.x); DUP2(ad[1], aA.y);
            DUP2(ad[2], aA.z); DUP2(ad[3], aA.w);
            DUP2(ad[4], aB.x); DUP2(ad[5], aB.y);
            DUP2(ad[6], aB.z); DUP2(ad[7], aB.w);
#pragma unroll
            for (int i = 0; i < 8; i++) {
                FMA2(acc[i][0], ad[i], b2.x);
                FMA2(acc[i][1], ad[i], b2.y);
            }
        }
    }

    float4 bb = *(const float4*)(bias_s + tx * 4);
#pragma unroll
    for (int i = 0; i < 8; i++) {
        float c0, c1, c2, c3;
        UNPACK2(c0, c1, acc[i][0]);
        UNPACK2(c2, c3, acc[i][1]);
        __half2 h0 = __floats2half2_rn(c0 + bb.x, c1 + bb.y);
        __half2 h1 = __floats2half2_rn(c2 + bb.z, c3 + bb.w);
        int row = rb + ty * 8 + i;
        __half2* dst = (__half2*)&g_tableh[(size_t)row * NC + cb + tx * 4];
        dst[0] = h0;
        dst[1] = h1;
    }
}

// ---------------------------------------------------------------------------
// Kernel 2: LSTM recurrence. 4 chains per block, 128 blocks (one wave).
// Thread (warp w, lane l): gate slot g=l>>3, cell e=w*8+(l&7), row j=g*64+e.
// One __syncthreads per step; 4x4 shfl transpose; xp gathered from the
// fp16 L2-resident table with 1-step prefetch.
// ---------------------------------------------------------------------------
#define HS 68   // padded h row stride (floats)

__global__ __launch_bounds__(256)
void lstm_rec(const int* __restrict__ x,
              const float* __restrict__ Whh_f,
              const float* __restrict__ Whh_b)
{
    const int tid  = threadIdx.x;
    const int lane = tid & 31;
    const int w    = tid >> 5;
    const int g    = lane >> 3;
    const int i8   = lane & 7;
    const int e    = w * 8 + i8;
    const int j    = g * 64 + e;

    const int bg  = blockIdx.x;
    const int dir = blockIdx.y;
    const float* __restrict__ W = dir ? Whh_b : Whh_f;

    __shared__ int toks[4][Sz];
    __shared__ __align__(16) float h_sh[2][4 * HS];

    for (int p = tid; p < 4 * Sz; p += 256) {
        int r = p >> 9, t = p & 511;
        toks[r][t] = x[(bg * 4 + r) * Sz + t];
    }
    for (int p = tid; p < 4 * HS; p += 256) h_sh[0][p] = 0.0f;

    ulonglong2 wv[16];
    const ulonglong2* Wp = (const ulonglong2*)(W + j * Hz);
#pragma unroll
    for (int m = 0; m < 16; m++) wv[m] = Wp[m];

    float c = 0.0f, h_own = 0.0f;
    const __half* __restrict__ tb = g_tableh + dir * Gz + j;

    __syncthreads();

    int t = dir ? (Sz - 1) : 0;
    const int dt = dir ? -1 : 1;

    float xc[4];
#pragma unroll
    for (int r = 0; r < 4; r++) xc[r] = __half2float(tb[(size_t)toks[r][t] * NC]);

    int pb = 0;
#pragma unroll 1
    for (int s = 0; s < Sz; s++) {
        int tn = t + dt;
        float xn[4] = {0.f, 0.f, 0.f, 0.f};
        if (s < Sz - 1) {
#pragma unroll
            for (int r = 0; r < 4; r++)
                xn[r] = __half2float(tb[(size_t)toks[r][tn] * NC]);
        }

        // matvec: v[r] = xc[r] + dot(W_hh[j], h[r])
        unsigned long long accA[4], accB[4];
#pragma unroll
        for (int r = 0; r < 4; r++) {
            PACK2(accA[r], xc[r], 0.0f);
            accB[r] = 0ull;
        }
#pragma unroll
        for (int m = 0; m < 16; m++) {
#pragma unroll
            for (int r = 0; r < 4; r++) {
                ulonglong2 hv = *(const ulonglong2*)(h_sh[pb] + r * HS + 4 * m);
                FMA2(accA[r], wv[m].x, hv.x);
                FMA2(accB[r], wv[m].y, hv.y);
            }
        }
        float v[4];
#pragma unroll
        for (int r = 0; r < 4; r++) {
            unsigned long long acs;
            ADD2(acs, accA[r], accB[r]);
            float lo, hi;
            UNPACK2(lo, hi, acs);
            v[r] = lo + hi;
        }

        // 4x4 lane-group transpose
        float tq[4];
        tq[g] = v[g];
#pragma unroll
        for (int p = 1; p < 4; p++) {
            int send_idx = (g + p) & 3;
            int recv_idx = (g - p) & 3;
            int src = (recv_idx << 3) | i8;
            tq[recv_idx] = __shfl_sync(0xFFFFFFFFu, v[send_idx], src);
        }

        // update cell (chain g, cell e)
        {
            float gi = sigm_t(tq[0]);
            float gf = sigm_t(tq[1]);
            float gg = tanh_ap(tq[2]);
            float go = sigm_t(tq[3]);
            c = gf * c + gi * gg;
            h_own = go * tanh_ap(c);
            h_sh[pb ^ 1][g * HS + e] = h_own;
        }
        __syncthreads();

        pb ^= 1;
#pragma unroll
        for (int r = 0; r < 4; r++) xc[r] = xn[r];
        t = tn;
    }

    g_hfin[(size_t)(dir * Bz + bg * 4 + g) * Hz + e] = h_own;
}

// ---------------------------------------------------------------------------
// Kernel 3: final FC + sigmoid
// ---------------------------------------------------------------------------
__global__ void final_fc(const float* __restrict__ fcw,
                         const float* __restrict__ fcb,
                         float* __restrict__ out)
{
    int b = threadIdx.x;
    if (b >= Bz) return;
    float acc = fcb[0];
    const float* hf = g_hfin + b * Hz;
    const float* hb = g_hfin + Bz * Hz + b * Hz;
#pragma unroll
    for (int u = 0; u < Hz; u++) {
        acc = fmaf(hf[u], fcw[u], acc);
        acc = fmaf(hb[u], fcw[Hz + u], acc);
    }
    out[b] = __fdividef(1.0f, 1.0f + __expf(-acc));
}

// ---------------------------------------------------------------------------
extern "C" void kernel_launch(void* const* d_in, const int* in_sizes, int n_in,
                              void* d_out, int out_size)
{
    const int*   x     = (const int*)  d_in[0];
    const float* emb   = (const float*)d_in[1];
    const float* Wih_f = (const float*)d_in[2];
    const float* Whh_f = (const float*)d_in[3];
    const float* bih_f = (const float*)d_in[4];
    const float* bhh_f = (const float*)d_in[5];
    const float* Wih_b = (const float*)d_in[6];
    const float* Whh_b = (const float*)d_in[7];
    const float* bih_b = (const float*)d_in[8];
    const float* bhh_b = (const float*)d_in[9];
    const float* fcw   = (const float*)d_in[10];
    const float* fcb   = (const float*)d_in[11];
    float* out = (float*)d_out;

    dim3 g1(VP / 128, NC / 64);   // 391 x 8
    vocab_gemm<<<g1, 256>>>(emb, Wih_f, bih_f, bhh_f, Wih_b, bih_b, bhh_b);

    dim3 g2(Bz / 4, 2);           // 128 blocks, one wave
    lstm_rec<<<g2, 256>>>(x, Whh_f, Whh_b);

    final_fc<<<1, 256>>>(fcw, fcb, out);
}

// round 6
// speedup vs baseline: 1.6599x; 1.6599x over previous
#include <cuda_runtime.h>
#include <cuda_fp16.h>
#include <cuda_bf16.h>

#define Bz 256
#define Sz 512
#define Ez 100
#define Hz 64
#define Gz 256      // 4*H
#define Vz 50000
#define VP 50048    // padded vocab rows
#define NC 512      // 2 dirs * 256 gates

// Precomputed per-vocab input projections (+bias), fp16, layout [VP][NC]
__device__ __half g_tableh[(size_t)VP * NC];   // 51.2 MB (L2-resident)
__device__ float  g_hfin[2 * Bz * Hz];

// ---- f32x2 packed-math helpers (GEMM) ----
#define FMA2(acc, a, b) \
    asm("fma.rn.f32x2 %0, %1, %2, %0;" : "+l"(acc) : "l"(a), "l"(b))
#define DUP2(d, a) \
    asm("mov.b64 %0, {%1, %1};" : "=l"(d) : "f"(a))
#define UNPACK2(a, b, d) \
    asm("mov.b64 {%0, %1}, %2;" : "=f"(a), "=f"(b) : "l"(d))

__device__ __forceinline__ float tanh_ap(float x) {
    float y;
    asm("tanh.approx.f32 %0, %1;" : "=f"(y) : "f"(x));
    return y;
}
__device__ __forceinline__ float sigm_t(float x) {
    return fmaf(0.5f, tanh_ap(0.5f * x), 0.5f);
}

// ---------------------------------------------------------------------------
// Kernel 1: vocab-table GEMM (fp32 math, fp16 store). Unchanged from R4.
// ---------------------------------------------------------------------------
#define TKc 50
#define LDAa 132
#define LDBb 68

__global__ __launch_bounds__(256)
void vocab_gemm(const float* __restrict__ emb,
                const float* __restrict__ Wih_f,
                const float* __restrict__ bih_f,
                const float* __restrict__ bhh_f,
                const float* __restrict__ Wih_b,
                const float* __restrict__ bih_b,
                const float* __restrict__ bhh_b)
{
    const int tid = threadIdx.x;
    const int tx = tid & 15;
    const int ty = tid >> 4;
    const int rb = blockIdx.x * 128;
    const int cb = blockIdx.y * 64;
    const int dir = cb >> 8;
    const int gb  = cb & 255;

    const float* __restrict__ W  = dir ? Wih_b : Wih_f;
    const float* __restrict__ bi = dir ? bih_b : bih_f;
    const float* __restrict__ bh = dir ? bhh_b : bhh_f;

    __shared__ __align__(16) float As[TKc * LDAa];
    __shared__ __align__(16) float Bs[TKc * LDBb];
    __shared__ float bias_s[64];

    if (tid < 64) bias_s[tid] = bi[gb + tid] + bh[gb + tid];

    unsigned long long acc[8][2];
#pragma unroll
    for (int i = 0; i < 8; i++) { acc[i][0] = 0ull; acc[i][1] = 0ull; }

    const float2* __restrict__ emb2 = (const float2*)emb;
    const float2* __restrict__ W2   = (const float2*)W;

    for (int kc = 0; kc < Ez; kc += TKc) {
        if (kc) __syncthreads();
        for (int p = tid; p < 128 * 25; p += 256) {
            int q = p % 25;
            int m = p / 25;
            int row = rb + m; if (row >= Vz) row = Vz - 1;
            float2 va = emb2[(size_t)row * 50 + (kc >> 1) + q];
            As[(2 * q)     * LDAa + m] = va.x;
            As[(2 * q + 1) * LDAa + m] = va.y;
        }
        for (int p = tid; p < 64 * 25; p += 256) {
            int q = p % 25;
            int m = p / 25;
            float2 vb = W2[(size_t)(gb + m) * 50 + (kc >> 1) + q];
            Bs[(2 * q)     * LDBb + m] = vb.x;
            Bs[(2 * q + 1) * LDBb + m] = vb.y;
        }
        __syncthreads();

#pragma unroll 5
        for (int k = 0; k < TKc; k++) {
            float4 aA = *(const float4*)(As + k * LDAa + ty * 8);
            float4 aB = *(const float4*)(As + k * LDAa + ty * 8 + 4);
            ulonglong2 b2 = *(const ulonglong2*)(Bs + k * LDBb + tx * 4);
            unsigned long long ad[8];
            DUP2(ad[0], aA.x); DUP2(ad[1], aA.y);
            DUP2(ad[2], aA.z); DUP2(ad[3], aA.w);
            DUP2(ad[4], aB.x); DUP2(ad[5], aB.y);
            DUP2(ad[6], aB.z); DUP2(ad[7], aB.w);
#pragma unroll
            for (int i = 0; i < 8; i++) {
                FMA2(acc[i][0], ad[i], b2.x);
                FMA2(acc[i][1], ad[i], b2.y);
            }
        }
    }

    float4 bb = *(const float4*)(bias_s + tx * 4);
#pragma unroll
    for (int i = 0; i < 8; i++) {
        float c0, c1, c2, c3;
        UNPACK2(c0, c1, acc[i][0]);
        UNPACK2(c2, c3, acc[i][1]);
        __half2 h0 = __floats2half2_rn(c0 + bb.x, c1 + bb.y);
        __half2 h1 = __floats2half2_rn(c2 + bb.z, c3 + bb.w);
        int row = rb + ty * 8 + i;
        __half2* dst = (__half2*)&g_tableh[(size_t)row * NC + cb + tx * 4];
        dst[0] = h0;
        dst[1] = h1;
    }
}

// ---------------------------------------------------------------------------
// Kernel 2: LSTM recurrence via warp-level HMMA (mma.sync.m16n8k16 f16->f32).
// 4 real chains (+4 zero-pad) per block; 64 bg x 2 dir = 128 blocks = 1 wave.
// 8 warps; warp w owns gate rows [32w, 32w+32) as 2 m-tiles; A = W_hh frags
// resident in registers; B = h (fp16, smem); C init = gathered x-projection.
// Update phase: thread tid -> (chain n=tid>>6, cell e=tid&63), c kept fp32.
// ---------------------------------------------------------------------------
#define HP 72    // h smem row stride (halfs): conflict-free B-frag LDS
#define GP 10    // gates smem row stride (floats): 8B-aligned STS.b64

__global__ __launch_bounds__(256)
void lstm_rec(const int* __restrict__ x,
              const float* __restrict__ Whh_f,
              const float* __restrict__ Whh_b)
{
    const int tid  = threadIdx.x;
    const int lane = tid & 31;
    const int w    = tid >> 5;          // warp 0..7
    const int gid  = lane >> 2;         // 0..7
    const int tg   = lane & 3;          // 0..3

    const int bg  = blockIdx.x;         // batch group (4 rows)
    const int dir = blockIdx.y;
    const float* __restrict__ W = dir ? Whh_b : Whh_f;

    __shared__ int toks[4][Sz];
    __shared__ __align__(16) __half h_sh[8 * HP];      // [chain n][k] fp16
    __shared__ __align__(16) float  gates_sh[Gz * GP]; // [gate row][chain]

    for (int p = tid; p < 4 * Sz; p += 256) {
        int r = p >> 9, t = p & 511;
        toks[r][t] = x[(bg * 4 + r) * Sz + t];
    }
    for (int p = tid; p < 8 * HP; p += 256) h_sh[p] = __float2half(0.0f);

    // A fragments: W_hh rows [32w, 32w+32), 2 m-tiles x 4 k-tiles x 4 regs
    unsigned int afr[2][4][4];
#pragma unroll
    for (int mt = 0; mt < 2; mt++) {
        int R = w * 32 + mt * 16 + gid;
#pragma unroll
        for (int kt = 0; kt < 4; kt++) {
            int cbase = kt * 16 + tg * 2;
            const float* r0 = W + R * Hz;
            const float* r8 = W + (R + 8) * Hz;
            __half2 h0 = __floats2half2_rn(r0[cbase],     r0[cbase + 1]);
            __half2 h1 = __floats2half2_rn(r8[cbase],     r8[cbase + 1]);
            __half2 h2 = __floats2half2_rn(r0[cbase + 8], r0[cbase + 9]);
            __half2 h3 = __floats2half2_rn(r8[cbase + 8], r8[cbase + 9]);
            afr[mt][kt][0] = *(unsigned int*)&h0;
            afr[mt][kt][1] = *(unsigned int*)&h1;
            afr[mt][kt][2] = *(unsigned int*)&h2;
            afr[mt][kt][3] = *(unsigned int*)&h3;
        }
    }

    // C-fragment row bases for this thread (gate rows)
    const int row0 = w * 32 + gid;        // mt0 c0,c1
    const int row1 = row0 + 8;            // mt0 c2,c3
    const int row2 = row0 + 16;           // mt1 c0,c1
    const int row3 = row0 + 24;           // mt1 c2,c3
    const int n0   = tg * 2;              // C-fragment chains (n0, n0+1)
    const bool real = (n0 < 4);

    // update-phase ownership
    const int un = tid >> 6;              // chain 0..3
    const int ue = tid & 63;              // cell 0..63
    float cst = 0.0f;                     // cell state (fp32)

    const __half* __restrict__ tb = g_tableh + dir * Gz;

    __syncthreads();

    int t = dir ? (Sz - 1) : 0;
    const int dt = dir ? -1 : 1;

    // initial xp gather (C init for step 0): xc[mt*4 + {c0,c1,c2,c3}]
    float xc[8] = {0, 0, 0, 0, 0, 0, 0, 0};
    if (real) {
        size_t ra = (size_t)toks[n0][t] * NC;
        size_t rb_ = (size_t)toks[n0 + 1][t] * NC;
        xc[0] = __half2float(tb[ra + row0]);  xc[1] = __half2float(tb[rb_ + row0]);
        xc[2] = __half2float(tb[ra + row1]);  xc[3] = __half2float(tb[rb_ + row1]);
        xc[4] = __half2float(tb[ra + row2]);  xc[5] = __half2float(tb[rb_ + row2]);
        xc[6] = __half2float(tb[ra + row3]);  xc[7] = __half2float(tb[rb_ + row3]);
    }

#pragma unroll 1
    for (int s = 0; s < Sz; s++) {
        int tn = t + dt;
        // prefetch next step's xp
        float xn[8] = {0, 0, 0, 0, 0, 0, 0, 0};
        if (real && s < Sz - 1) {
            size_t ra = (size_t)toks[n0][tn] * NC;
            size_t rb_ = (size_t)toks[n0 + 1][tn] * NC;
            xn[0] = __half2float(tb[ra + row0]);  xn[1] = __half2float(tb[rb_ + row0]);
            xn[2] = __half2float(tb[ra + row1]);  xn[3] = __half2float(tb[rb_ + row1]);
            xn[4] = __half2float(tb[ra + row2]);  xn[5] = __half2float(tb[rb_ + row2]);
            xn[6] = __half2float(tb[ra + row3]);  xn[7] = __half2float(tb[rb_ + row3]);
        }

        // B fragments from h_sh: b0 = h[n=gid][kt*16 + tg*2 + {0,1}], b1 = +8
        unsigned int b0[4], b1[4];
#pragma unroll
        for (int kt = 0; kt < 4; kt++) {
            const unsigned int* hw =
                (const unsigned int*)(h_sh + gid * HP + kt * 16 + tg * 2);
            b0[kt] = hw[0];
            b1[kt] = hw[4];   // +8 halfs
        }

        // 2 m-tiles x 4 k-steps of HMMA; C initialized with xp gather
#pragma unroll
        for (int mt = 0; mt < 2; mt++) {
            float c0 = xc[mt * 4 + 0], c1 = xc[mt * 4 + 1];
            float c2 = xc[mt * 4 + 2], c3 = xc[mt * 4 + 3];
#pragma unroll
            for (int kt = 0; kt < 4; kt++) {
                asm("mma.sync.aligned.m16n8k16.row.col.f32.f16.f16.f32 "
                    "{%0,%1,%2,%3}, {%4,%5,%6,%7}, {%8,%9}, {%0,%1,%2,%3};"
                    : "+f"(c0), "+f"(c1), "+f"(c2), "+f"(c3)
                    : "r"(afr[mt][kt][0]), "r"(afr[mt][kt][1]),
                      "r"(afr[mt][kt][2]), "r"(afr[mt][kt][3]),
                      "r"(b0[kt]), "r"(b1[kt]));
            }
            int ra = w * 32 + mt * 16 + gid;
            *(float2*)&gates_sh[ra * GP + n0]       = make_float2(c0, c1);
            *(float2*)&gates_sh[(ra + 8) * GP + n0] = make_float2(c2, c3);
        }
        __syncthreads();

        // cell update: chain un, cell ue
        {
            float gi = sigm_t(gates_sh[ue * GP + un]);
            float gf = sigm_t(gates_sh[(Hz + ue) * GP + un]);
            float gg = tanh_ap(gates_sh[(2 * Hz + ue) * GP + un]);
            float go = sigm_t(gates_sh[(3 * Hz + ue) * GP + un]);
            cst = gf * cst + gi * gg;
            h_sh[un * HP + ue] = __float2half(go * tanh_ap(cst));
        }
        __syncthreads();

#pragma unroll
        for (int q = 0; q < 8; q++) xc[q] = xn[q];
        t = tn;
    }

    g_hfin[(size_t)(dir * Bz + bg * 4 + un) * Hz + ue] =
        __half2float(h_sh[un * HP + ue]);
}

// ---------------------------------------------------------------------------
// Kernel 3: final FC + sigmoid
// ---------------------------------------------------------------------------
__global__ void final_fc(const float* __restrict__ fcw,
                         const float* __restrict__ fcb,
                         float* __restrict__ out)
{
    int b = threadIdx.x;
    if (b >= Bz) return;
    float acc = fcb[0];
    const float* hf = g_hfin + b * Hz;
    const float* hb = g_hfin + Bz * Hz + b * Hz;
#pragma unroll
    for (int u = 0; u < Hz; u++) {
        acc = fmaf(hf[u], fcw[u], acc);
        acc = fmaf(hb[u], fcw[Hz + u], acc);
    }
    out[b] = __fdividef(1.0f, 1.0f + __expf(-acc));
}

// ---------------------------------------------------------------------------
extern "C" void kernel_launch(void* const* d_in, const int* in_sizes, int n_in,
                              void* d_out, int out_size)
{
    const int*   x     = (const int*)  d_in[0];
    const float* emb   = (const float*)d_in[1];
    const float* Wih_f = (const float*)d_in[2];
    const float* Whh_f = (const float*)d_in[3];
    const float* bih_f = (const float*)d_in[4];
    const float* bhh_f = (const float*)d_in[5];
    const float* Wih_b = (const float*)d_in[6];
    const float* Whh_b = (const float*)d_in[7];
    const float* bih_b = (const float*)d_in[8];
    const float* bhh_b = (const float*)d_in[9];
    const float* fcw   = (const float*)d_in[10];
    const float* fcb   = (const float*)d_in[11];
    float* out = (float*)d_out;

    dim3 g1(VP / 128, NC / 64);   // 391 x 8
    vocab_gemm<<<g1, 256>>>(emb, Wih_f, bih_f, bhh_f, Wih_b, bih_b, bhh_b);

    dim3 g2(Bz / 4, 2);           // 128 blocks, one wave
    lstm_rec<<<g2, 256>>>(x, Whh_f, Whh_b);

    final_fc<<<1, 256>>>(fcw, fcb, out);
}

// round 7
// speedup vs baseline: 1.9759x; 1.1904x over previous
#include <cuda_runtime.h>
#include <cuda_fp16.h>
#include <cuda_bf16.h>

#define Bz 256
#define Sz 512
#define Ez 100
#define Hz 64
#define Gz 256      // 4*H
#define Vz 50000
#define VP 50048    // padded vocab rows (391*128)
#define NC 512      // 2 dirs * 256 gates

// Precomputed per-vocab input projections (+bias), fp16, layout [VP][NC]
__device__ __half g_tableh[(size_t)VP * NC];   // 51.2 MB (L2-resident)
__device__ float  g_hfin[2 * Bz * Hz];

__device__ __forceinline__ float tanh_ap(float x) {
    float y;
    asm("tanh.approx.f32 %0, %1;" : "=f"(y) : "f"(x));
    return y;
}
__device__ __forceinline__ unsigned int tanh2_ap(unsigned int x) {
    unsigned int y;
    asm("tanh.approx.f16x2 %0, %1;" : "=r"(y) : "r"(x));
    return y;
}

#define MMA16816(c0,c1,c2,c3, a0,a1,a2,a3, b0,b1) \
    asm("mma.sync.aligned.m16n8k16.row.col.f32.f16.f16.f32 " \
        "{%0,%1,%2,%3}, {%4,%5,%6,%7}, {%8,%9}, {%0,%1,%2,%3};" \
        : "+f"(c0), "+f"(c1), "+f"(c2), "+f"(c3) \
        : "r"(a0), "r"(a1), "r"(a2), "r"(a3), "r"(b0), "r"(b1))

// ---------------------------------------------------------------------------
// Kernel 1: vocab-table GEMM via HMMA (fp16 in, fp32 accum, fp16 store).
//   table[v, dir*256+g] = sum_k emb[v,k]*W_ih[g,k] + (b_ih[g]+b_hh[g])
//   Tile 128(M) x 64(N) x 112(K, zero-padded from 100). 8 warps (4M x 2N),
//   each 32x32 via 2 m-frags x 4 n-frags x 7 k-tiles. Smem stride 120 halfs
//   (conflict-free fragment LDS).
// ---------------------------------------------------------------------------
#define KP 112     // padded K
#define LDH 120    // smem row stride in halfs

__global__ __launch_bounds__(256)
void vocab_gemm(const float* __restrict__ emb,
                const float* __restrict__ Wih_f,
                const float* __restrict__ bih_f,
                const float* __restrict__ bhh_f,
                const float* __restrict__ Wih_b,
                const float* __restrict__ bih_b,
                const float* __restrict__ bhh_b)
{
    const int tid  = threadIdx.x;
    const int lane = tid & 31;
    const int w    = tid >> 5;
    const int gid  = lane >> 2;
    const int tg   = lane & 3;
    const int wm   = w & 3;       // M warp 0..3 (32 rows each)
    const int wn   = w >> 2;      // N warp 0..1 (32 cols each)

    const int rb = blockIdx.x * 128;
    const int cb = blockIdx.y * 64;
    const int dir = cb >> 8;
    const int gb  = cb & 255;

    const float* __restrict__ W  = dir ? Wih_b : Wih_f;
    const float* __restrict__ bi = dir ? bih_b : bih_f;
    const float* __restrict__ bh = dir ? bhh_b : bhh_f;

    __shared__ __align__(16) __half As[128 * LDH];
    __shared__ __align__(16) __half Bs[64 * LDH];
    __shared__ float bias_s[64];

    if (tid < 64) bias_s[tid] = bi[gb + tid] + bh[gb + tid];

    const float2* __restrict__ emb2 = (const float2*)emb;
    const float2* __restrict__ W2   = (const float2*)W;
    __half2* As2 = (__half2*)As;
    __half2* Bs2 = (__half2*)Bs;

    // Stage A: 128 rows x 50 float2 -> fp16
    for (int p = tid; p < 128 * 50; p += 256) {
        int m = p / 50, q = p - m * 50;
        int row = rb + m; if (row >= Vz) row = Vz - 1;
        float2 v = emb2[(size_t)row * 50 + q];
        As2[m * (LDH / 2) + q] = __floats2half2_rn(v.x, v.y);
    }
    // Zero A k-tail (halfs 100..111 -> half2 idx 50..55)
    for (int p = tid; p < 128 * 6; p += 256) {
        int m = p / 6, q = 50 + (p - m * 6);
        As2[m * (LDH / 2) + q] = __half2half2(__float2half(0.0f));
    }
    // Stage B: 64 rows x 50 float2
    for (int p = tid; p < 64 * 50; p += 256) {
        int m = p / 50, q = p - m * 50;
        float2 v = W2[(size_t)(gb + m) * 50 + q];
        Bs2[m * (LDH / 2) + q] = __floats2half2_rn(v.x, v.y);
    }
    for (int p = tid; p < 64 * 6; p += 256) {
        int m = p / 6, q = 50 + (p - m * 6);
        Bs2[m * (LDH / 2) + q] = __half2half2(__float2half(0.0f));
    }
    __syncthreads();

    float acc[2][4][4];
#pragma unroll
    for (int mt = 0; mt < 2; mt++)
#pragma unroll
        for (int nt = 0; nt < 4; nt++)
#pragma unroll
            for (int i = 0; i < 4; i++) acc[mt][nt][i] = 0.0f;

#pragma unroll
    for (int kt = 0; kt < 7; kt++) {
        unsigned int a[2][4], b[4][2];
#pragma unroll
        for (int mt = 0; mt < 2; mt++) {
            int r = wm * 32 + mt * 16 + gid;
            const unsigned int* p0 = (const unsigned int*)(As + r * LDH + kt * 16 + 2 * tg);
            const unsigned int* p1 = (const unsigned int*)(As + (r + 8) * LDH + kt * 16 + 2 * tg);
            a[mt][0] = p0[0];
            a[mt][1] = p1[0];
            a[mt][2] = p0[4];   // k + 8 halfs
            a[mt][3] = p1[4];
        }
#pragma unroll
        for (int nt = 0; nt < 4; nt++) {
            int n = wn * 32 + nt * 8 + gid;
            const unsigned int* p = (const unsigned int*)(Bs + n * LDH + kt * 16 + 2 * tg);
            b[nt][0] = p[0];
            b[nt][1] = p[4];
        }
#pragma unroll
        for (int mt = 0; mt < 2; mt++)
#pragma unroll
            for (int nt = 0; nt < 4; nt++)
                MMA16816(acc[mt][nt][0], acc[mt][nt][1], acc[mt][nt][2], acc[mt][nt][3],
                         a[mt][0], a[mt][1], a[mt][2], a[mt][3],
                         b[nt][0], b[nt][1]);
    }

    // Epilogue: +bias, fp16 store
#pragma unroll
    for (int mt = 0; mt < 2; mt++) {
#pragma unroll
        for (int nt = 0; nt < 4; nt++) {
            int n = wn * 32 + nt * 8 + 2 * tg;      // local col of c0
            float b0 = bias_s[n], b1 = bias_s[n + 1];
            int r0 = rb + wm * 32 + mt * 16 + gid;
            int r1 = r0 + 8;
            *(__half2*)&g_tableh[(size_t)r0 * NC + cb + n] =
                __floats2half2_rn(acc[mt][nt][0] + b0, acc[mt][nt][1] + b1);
            *(__half2*)&g_tableh[(size_t)r1 * NC + cb + n] =
                __floats2half2_rn(acc[mt][nt][2] + b0, acc[mt][nt][3] + b1);
        }
    }
}

// ---------------------------------------------------------------------------
// Kernel 2: LSTM recurrence, HMMA with permuted-gate A packing.
// 4 chains (+4 pad) per block; 64 bg x 2 dir = 128 blocks = 1 wave; 8 warps.
// Warp w owns cells e in [8w, 8w+8). Packed A rows (p = mt*16 + {gid, gid+8}):
//   mt0: p=gid -> i-gate(e), p=gid+8 -> f-gate(e)
//   mt1: p=16+gid -> g-gate(e), p=24+gid -> o-gate(e)      with e = 8w+gid.
// => thread (w,gid,tg) receives i,f,g,o of cell e for chains 2tg, 2tg+1:
// the cell update is THREAD-LOCAL (no gates smem, no transpose, 1 BAR/step).
// ---------------------------------------------------------------------------
#define HP 72    // h smem row stride (halfs): conflict-free B-frag LDS

__global__ __launch_bounds__(256)
void lstm_rec(const int* __restrict__ x,
              const float* __restrict__ Whh_f,
              const float* __restrict__ Whh_b)
{
    const int tid  = threadIdx.x;
    const int lane = tid & 31;
    const int w    = tid >> 5;          // warp 0..7
    const int gid  = lane >> 2;         // 0..7
    const int tg   = lane & 3;          // 0..3
    const int e    = w * 8 + gid;       // owned cell 0..63
    const int n0   = 2 * tg;            // chains n0, n0+1 (real if tg<2)
    const bool real = (tg < 2);

    const int bg  = blockIdx.x;
    const int dir = blockIdx.y;
    const float* __restrict__ W = dir ? Whh_b : Whh_f;

    __shared__ int toks[4][Sz];
    __shared__ __align__(16) __half h_sh[2][8 * HP];   // [buf][chain][k]

    for (int p = tid; p < 4 * Sz; p += 256) {
        int r = p >> 9, t = p & 511;
        toks[r][t] = x[(bg * 4 + r) * Sz + t];
    }
    for (int p = tid; p < 2 * 8 * HP; p += 256)
        ((__half*)h_sh)[p] = __float2half(0.0f);

    // A fragments with permuted-gate packing:
    // afr[mt][kt]: reg0/2 = gate 2mt row (cell e), reg1/3 = gate 2mt+1 row.
    unsigned int afr[2][4][4];
#pragma unroll
    for (int mt = 0; mt < 2; mt++) {
        const float* r0 = W + (size_t)((2 * mt)     * 64 + e) * Hz;
        const float* r1 = W + (size_t)((2 * mt + 1) * 64 + e) * Hz;
#pragma unroll
        for (int kt = 0; kt < 4; kt++) {
            int cb_ = kt * 16 + tg * 2;
            __half2 h0 = __floats2half2_rn(r0[cb_],     r0[cb_ + 1]);
            __half2 h1 = __floats2half2_rn(r1[cb_],     r1[cb_ + 1]);
            __half2 h2 = __floats2half2_rn(r0[cb_ + 8], r0[cb_ + 9]);
            __half2 h3 = __floats2half2_rn(r1[cb_ + 8], r1[cb_ + 9]);
            afr[mt][kt][0] = *(unsigned int*)&h0;
            afr[mt][kt][1] = *(unsigned int*)&h1;
            afr[mt][kt][2] = *(unsigned int*)&h2;
            afr[mt][kt][3] = *(unsigned int*)&h3;
        }
    }

    float cst0 = 0.0f, cst1 = 0.0f;     // fp32 cell states (2 chains)
    float hout0 = 0.0f, hout1 = 0.0f;

    const __half* __restrict__ tb = g_tableh + dir * Gz;

    __syncthreads();

    int t = dir ? (Sz - 1) : 0;
    const int dt = dir ? -1 : 1;

    // xp gather: xc layout [mt*4+ci] matching C fragments:
    //   [0],[1]=i(e) chains n0,n0+1; [2],[3]=f; [4],[5]=g; [6],[7]=o
    float xc[8] = {0, 0, 0, 0, 0, 0, 0, 0};
    if (real) {
        size_t ba = (size_t)toks[n0][t] * NC;
        size_t bb = (size_t)toks[n0 + 1][t] * NC;
        xc[0] = __half2float(tb[ba + e]);        xc[1] = __half2float(tb[bb + e]);
        xc[2] = __half2float(tb[ba + 64 + e]);   xc[3] = __half2float(tb[bb + 64 + e]);
        xc[4] = __half2float(tb[ba + 128 + e]);  xc[5] = __half2float(tb[bb + 128 + e]);
        xc[6] = __half2float(tb[ba + 192 + e]);  xc[7] = __half2float(tb[bb + 192 + e]);
    }

    const unsigned int H05 = 0x38003800u;  // half2(0.5, 0.5)
    int pb = 0;

#pragma unroll 1
    for (int s = 0; s < Sz; s++) {
        int tn = t + dt;
        // prefetch next xp (L2-resident table)
        float xn[8] = {0, 0, 0, 0, 0, 0, 0, 0};
        if (real && s < Sz - 1) {
            size_t ba = (size_t)toks[n0][tn] * NC;
            size_t bb = (size_t)toks[n0 + 1][tn] * NC;
            xn[0] = __half2float(tb[ba + e]);        xn[1] = __half2float(tb[bb + e]);
            xn[2] = __half2float(tb[ba + 64 + e]);   xn[3] = __half2float(tb[bb + 64 + e]);
            xn[4] = __half2float(tb[ba + 128 + e]);  xn[5] = __half2float(tb[bb + 128 + e]);
            xn[6] = __half2float(tb[ba + 192 + e]);  xn[7] = __half2float(tb[bb + 192 + e]);
        }

        // B fragments: b0 = {h[n=gid][kt16+2tg], +1}, b1 = +8 halfs
        unsigned int b0[4], b1[4];
#pragma unroll
        for (int kt = 0; kt < 4; kt++) {
            const unsigned int* hw =
                (const unsigned int*)(h_sh[pb] + gid * HP + kt * 16 + tg * 2);
            b0[kt] = hw[0];
            b1[kt] = hw[4];
        }

        float cc[2][4];
#pragma unroll
        for (int mt = 0; mt < 2; mt++) {
            cc[mt][0] = xc[mt * 4 + 0]; cc[mt][1] = xc[mt * 4 + 1];
            cc[mt][2] = xc[mt * 4 + 2]; cc[mt][3] = xc[mt * 4 + 3];
#pragma unroll
            for (int kt = 0; kt < 4; kt++)
                MMA16816(cc[mt][0], cc[mt][1], cc[mt][2], cc[mt][3],
                         afr[mt][kt][0], afr[mt][kt][1],
                         afr[mt][kt][2], afr[mt][kt][3],
                         b0[kt], b1[kt]);
        }

        // thread-local cell update (chains n0, n0+1 at cell e)
        if (real) {
            __half2 pi = __floats2half2_rn(cc[0][0], cc[0][1]);
            __half2 pf = __floats2half2_rn(cc[0][2], cc[0][3]);
            __half2 pg = __floats2half2_rn(cc[1][0], cc[1][1]);
            __half2 po = __floats2half2_rn(cc[1][2], cc[1][3]);
            unsigned int ui = *(unsigned int*)&pi;
            unsigned int uf = *(unsigned int*)&pf;
            unsigned int ug = *(unsigned int*)&pg;
            unsigned int uo = *(unsigned int*)&po;
            // sigmoid(x) = 0.5*tanh(0.5x)+0.5 in packed f16x2
            unsigned int si, sf, so, tg2;
            asm("{ .reg .b32 tmp;\n\t"
                "mul.f16x2 tmp, %1, %2;\n\t"
                "tanh.approx.f16x2 tmp, tmp;\n\t"
                "fma.rn.f16x2 %0, tmp, %2, %2; }"
                : "=r"(si) : "r"(ui), "r"(H05));
            asm("{ .reg .b32 tmp;\n\t"
                "mul.f16x2 tmp, %1, %2;\n\t"
                "tanh.approx.f16x2 tmp, tmp;\n\t"
                "fma.rn.f16x2 %0, tmp, %2, %2; }"
                : "=r"(sf) : "r"(uf), "r"(H05));
            asm("{ .reg .b32 tmp;\n\t"
                "mul.f16x2 tmp, %1, %2;\n\t"
                "tanh.approx.f16x2 tmp, tmp;\n\t"
                "fma.rn.f16x2 %0, tmp, %2, %2; }"
                : "=r"(so) : "r"(uo), "r"(H05));
            tg2 = tanh2_ap(ug);

            __half2 hsi = *(__half2*)&si, hsf = *(__half2*)&sf;
            __half2 hso = *(__half2*)&so, htg = *(__half2*)&tg2;
            float si0 = __low2float(hsi), si1 = __high2float(hsi);
            float sf0 = __low2float(hsf), sf1 = __high2float(hsf);
            float so0 = __low2float(hso), so1 = __high2float(hso);
            float tg0 = __low2float(htg), tg1 = __high2float(htg);

            cst0 = sf0 * cst0 + si0 * tg0;
            cst1 = sf1 * cst1 + si1 * tg1;
            hout0 = so0 * tanh_ap(cst0);
            hout1 = so1 * tanh_ap(cst1);
            h_sh[pb ^ 1][n0 * HP + e]       = __float2half(hout0);
            h_sh[pb ^ 1][(n0 + 1) * HP + e] = __float2half(hout1);
        }
        __syncthreads();

        pb ^= 1;
#pragma unroll
        for (int q = 0; q < 8; q++) xc[q] = xn[q];
        t = tn;
    }

    if (real) {
        g_hfin[(size_t)(dir * Bz + bg * 4 + n0) * Hz + e]     = hout0;
        g_hfin[(size_t)(dir * Bz + bg * 4 + n0 + 1) * Hz + e] = hout1;
    }
}

// ---------------------------------------------------------------------------
// Kernel 3: final FC + sigmoid
// ---------------------------------------------------------------------------
__global__ void final_fc(const float* __restrict__ fcw,
                         const float* __restrict__ fcb,
                         float* __restrict__ out)
{
    int b = threadIdx.x;
    if (b >= Bz) return;
    float acc = fcb[0];
    const float* hf = g_hfin + b * Hz;
    const float* hb = g_hfin + Bz * Hz + b * Hz;
#pragma unroll
    for (int u = 0; u < Hz; u++) {
        acc = fmaf(hf[u], fcw[u], acc);
        acc = fmaf(hb[u], fcw[Hz + u], acc);
    }
    out[b] = __fdividef(1.0f, 1.0f + __expf(-acc));
}

// ---------------------------------------------------------------------------
extern "C" void kernel_launch(void* const* d_in, const int* in_sizes, int n_in,
                              void* d_out, int out_size)
{
    const int*   x     = (const int*)  d_in[0];
    const float* emb   = (const float*)d_in[1];
    const float* Wih_f = (const float*)d_in[2];
    const float* Whh_f = (const float*)d_in[3];
    const float* bih_f = (const float*)d_in[4];
    const float* bhh_f = (const float*)d_in[5];
    const float* Wih_b = (const float*)d_in[6];
    const float* Whh_b = (const float*)d_in[7];
    const float* bih_b = (const float*)d_in[8];
    const float* bhh_b = (const float*)d_in[9];
    const float* fcw   = (const float*)d_in[10];
    const float* fcb   = (const float*)d_in[11];
    float* out = (float*)d_out;

    dim3 g1(VP / 128, NC / 64);   // 391 x 8
    vocab_gemm<<<g1, 256>>>(emb, Wih_f, bih_f, bhh_f, Wih_b, bih_b, bhh_b);

    dim3 g2(Bz / 4, 2);           // 128 blocks, one wave
    lstm_rec<<<g2, 256>>>(x, Whh_f, Whh_b);

    final_fc<<<1, 256>>>(fcw, fcb, out);
}